// round 4
// baseline (speedup 1.0000x reference)
#include <cuda_runtime.h>

// IF (integrate-and-fire) scan. x: (B=32, T=8, CHW=200704) fp32.
// R4: two float4 streams per thread (p and p+256 within a 512-float4 CTA
// tile) -> 16 front-batched loads/thread, half the grid, half the index
// math. Both streams stay perfectly coalesced (unit lane stride).
// Plateau so far: 57.7us kernel @ DRAM 77.7% (R1/R3 identical).

#define T_STEPS 8
#define BATCH 32
#define CHW4 50176              // (64*56*56)/4 float4 per timestep-slice
#define VTH 1.0f
#define TILE 512                // float4s per CTA (2 per thread)

__global__ void __launch_bounds__(256) if_scan_kernel(
    const float4* __restrict__ x, float4* __restrict__ out)
{
    // grid covers BATCH * CHW4 / TILE CTAs; CHW4 = 50176 = 98 * 512 exactly.
    const int tile = blockIdx.x;                  // 0 .. 32*98-1
    const int b = tile / (CHW4 / TILE);           // 98 tiles per batch slice
    const int pt = tile - b * (CHW4 / TILE);
    const int p0 = pt * TILE + threadIdx.x;       // first float4
    const long long base0 = (long long)b * T_STEPS * CHW4 + p0;
    const long long base1 = base0 + 256;          // second float4 stream

    // Front-batch all 16 loads (scan-independent) -> deep MLP
    float4 a[T_STEPS], c[T_STEPS];
#pragma unroll
    for (int t = 0; t < T_STEPS; t++) {
        a[t] = x[base0 + (long long)t * CHW4];
        c[t] = x[base1 + (long long)t * CHW4];
    }

    float ax = 0.f, ay = 0.f, az = 0.f, aw = 0.f;
    float cx = 0.f, cy = 0.f, cz = 0.f, cw = 0.f;
#pragma unroll
    for (int t = 0; t < T_STEPS; t++) {
        ax += a[t].x; ay += a[t].y; az += a[t].z; aw += a[t].w;
        cx += c[t].x; cy += c[t].y; cz += c[t].z; cw += c[t].w;
        float4 s0, s1;
        s0.x = (ax > VTH) ? 1.0f : 0.0f;  s1.x = (cx > VTH) ? 1.0f : 0.0f;
        s0.y = (ay > VTH) ? 1.0f : 0.0f;  s1.y = (cy > VTH) ? 1.0f : 0.0f;
        s0.z = (az > VTH) ? 1.0f : 0.0f;  s1.z = (cz > VTH) ? 1.0f : 0.0f;
        s0.w = (aw > VTH) ? 1.0f : 0.0f;  s1.w = (cw > VTH) ? 1.0f : 0.0f;
        ax = (ax > VTH) ? 0.0f : ax;      cx = (cx > VTH) ? 0.0f : cx;
        ay = (ay > VTH) ? 0.0f : ay;      cy = (cy > VTH) ? 0.0f : cy;
        az = (az > VTH) ? 0.0f : az;      cz = (cz > VTH) ? 0.0f : cz;
        aw = (aw > VTH) ? 0.0f : aw;      cw = (cw > VTH) ? 0.0f : cw;
        out[base0 + (long long)t * CHW4] = s0;
        out[base1 + (long long)t * CHW4] = s1;
    }
}

extern "C" void kernel_launch(void* const* d_in, const int* in_sizes, int n_in,
                              void* d_out, int out_size)
{
    const float4* x = (const float4*)d_in[0];
    float4* out = (float4*)d_out;
    const int blocks = BATCH * (CHW4 / TILE);   // 32 * 98 = 3136
    if_scan_kernel<<<blocks, 256>>>(x, out);
}

// round 5
// speedup vs baseline: 1.0183x; 1.0183x over previous
#include <cuda_runtime.h>

// IF (integrate-and-fire) scan. x: (B=32, T=8, CHW=200704) fp32.
// Final form: R1/R3 structure (one float4 per thread across 8 timesteps,
// exact grid, front-batched loads) with BOTH streams marked evict-first
// (touch-once data, L2 as staging only).
// Evidence: R1 (plain), R3 (stcs), R4 (2x unroll) all plateau at
// ~6.15 TB/s DRAM = ~77% of spec — the 1:1 R/W HBM turnaround ceiling.

#define T_STEPS 8
#define BATCH 32
#define CHW4 50176              // (64*56*56)/4 float4 per timestep-slice
#define VTH 1.0f

__global__ void __launch_bounds__(256) if_scan_kernel(
    const float4* __restrict__ x, float4* __restrict__ out)
{
    const long long idx = (long long)blockIdx.x * blockDim.x + threadIdx.x;
    const long long total = (long long)BATCH * CHW4;   // 1,605,632
    if (idx >= total) return;

    const int b = (int)(idx / CHW4);
    const int p = (int)(idx % CHW4);
    const long long base = (long long)b * T_STEPS * CHW4 + p;

    // Front-batch all 8 loads (independent of scan state) -> MLP=8
    float4 xt[T_STEPS];
#pragma unroll
    for (int t = 0; t < T_STEPS; t++)
        xt[t] = __ldcs(x + base + (long long)t * CHW4);

    float mx = 0.f, my = 0.f, mz = 0.f, mw = 0.f;
#pragma unroll
    for (int t = 0; t < T_STEPS; t++) {
        mx += xt[t].x; my += xt[t].y; mz += xt[t].z; mw += xt[t].w;
        float4 s;
        s.x = (mx > VTH) ? 1.0f : 0.0f;
        s.y = (my > VTH) ? 1.0f : 0.0f;
        s.z = (mz > VTH) ? 1.0f : 0.0f;
        s.w = (mw > VTH) ? 1.0f : 0.0f;
        mx = (mx > VTH) ? 0.0f : mx;
        my = (my > VTH) ? 0.0f : my;
        mz = (mz > VTH) ? 0.0f : mz;
        mw = (mw > VTH) ? 0.0f : mw;
        __stcs(out + base + (long long)t * CHW4, s);
    }
}

extern "C" void kernel_launch(void* const* d_in, const int* in_sizes, int n_in,
                              void* d_out, int out_size)
{
    const float4* x = (const float4*)d_in[0];
    float4* out = (float4*)d_out;
    const long long total = (long long)BATCH * CHW4;
    const int threads = 256;
    const int blocks = (int)((total + threads - 1) / threads);
    if_scan_kernel<<<blocks, threads>>>(x, out);
}